// round 2
// baseline (speedup 1.0000x reference)
#include <cuda_runtime.h>
#include <cstdint>

#define NN 150000
#define EE 300000
#define BB 4096
#define DIN 155
#define DE 6
#define HIDN 256
#define LNUM 4
#define NH 4
#define CH 64
#define EA (EE + NN)
#define NEG 0.2f
#define BNEPS 1e-5f

// ---------------- device scratch (static: no allocations allowed) ----------------
__device__ float    g_bufA[(size_t)NN * HIDN];
__device__ float    g_bufB[(size_t)NN * HIDN];
__device__ float    g_xh[(size_t)NN * HIDN];
__device__ float    g_as[NN * NH];
__device__ float    g_ad[NN * NH];
__device__ float    g_ex[(size_t)EA * NH];     // logits, then exp(logits - m) in-place
__device__ unsigned g_mmax[NN * NH];
__device__ float    g_denom[NN * NH];
__device__ float    g_deg[NN];
__device__ float    g_lattr[NN * DE];
__device__ float    g_v[LNUM * DE * NH];       // edge_W[l] @ att_edge[l]  -> [DE, NH] per layer
__device__ float    g_mu[HIDN];
__device__ float    g_sq[HIDN];
__device__ float    g_cnt[BB];
__device__ float    g_gsum[BB * HIDN];
__device__ float    g_z1[BB * 128];
__device__ float    g_z2[BB * 64];

// monotone float <-> uint encoding for atomicMax over signed floats
__device__ __forceinline__ unsigned fenc(float x) {
    unsigned u = __float_as_uint(x);
    return (u & 0x80000000u) ? ~u : (u | 0x80000000u);
}
__device__ __forceinline__ float fdec(unsigned u) {
    return (u & 0x80000000u) ? __uint_as_float(u & 0x7FFFFFFFu) : __uint_as_float(~u);
}

// vector reduction: one REDG for 4 consecutive floats (sm_90+)
__device__ __forceinline__ void red4(float* addr, float a, float b, float c, float d) {
    asm volatile("red.global.add.v4.f32 [%0], {%1, %2, %3, %4};"
                 :: "l"(addr), "f"(a), "f"(b), "f"(c), "f"(d) : "memory");
}

// ---------------- self-loop attr: deg + sum of incoming edge_attr ----------------
__global__ void k_loop_accum(const int* __restrict__ dst, const float* __restrict__ eattr,
                             float* __restrict__ deg, float* __restrict__ lattr) {
    int e = blockIdx.x * blockDim.x + threadIdx.x;
    if (e >= EE) return;
    int d = dst[e];
    atomicAdd(&deg[d], 1.0f);
#pragma unroll
    for (int j = 0; j < DE; j++) atomicAdd(&lattr[d * DE + j], eattr[(size_t)e * DE + j]);
}

__global__ void k_loop_fin(const float* __restrict__ deg, float* __restrict__ lattr) {
    int idx = blockIdx.x * blockDim.x + threadIdx.x;
    if (idx >= NN * DE) return;
    int n = idx / DE;
    lattr[idx] *= (1.0f / fmaxf(deg[n], 1.0f));
}

// ---------------- v[l][d][h] = sum_c edge_W[l][d][h*64+c] * att_edge[l][h][c] ----
__global__ void k_veatt(const float* __restrict__ edge_W, const float* __restrict__ att_edge,
                        float* __restrict__ v) {
    int l = blockIdx.x / DE, d = blockIdx.x % DE;
    int h = threadIdx.x >> 5, lane = threadIdx.x & 31;
    const float* wp = edge_W + (size_t)l * DE * HIDN + (size_t)d * HIDN + h * CH;
    const float* ap = att_edge + (size_t)l * NH * CH + h * CH;
    float s = wp[lane] * ap[lane] + wp[lane + 32] * ap[lane + 32];
#pragma unroll
    for (int o = 16; o > 0; o >>= 1) s += __shfl_xor_sync(0xFFFFFFFFu, s, o);
    if (lane == 0) v[blockIdx.x * NH + h] = s;
}

// ---------------- fp32 SGEMM: C = relu?(A[M,K] @ W[K,Nc] (+ bias)) --------------
__global__ __launch_bounds__(256) void k_sgemm(
    const float* __restrict__ A, const float* __restrict__ W,
    const float* __restrict__ bias, float* __restrict__ C,
    int M, int K, int Ncols, int doRelu)
{
    __shared__ float As[8][128];
    __shared__ float Bs[8][128];
    int tid = threadIdx.x;
    int bcol = blockIdx.x * 128;
    int brow = blockIdx.y * 128;
    int tr = (tid >> 4) * 8;
    int tc = (tid & 15) * 8;
    float acc[8][8];
#pragma unroll
    for (int i = 0; i < 8; i++)
#pragma unroll
        for (int j = 0; j < 8; j++) acc[i][j] = 0.0f;

    int arow = tid >> 1, acol = (tid & 1) * 4;
    int wrow = tid >> 5, wcol = (tid & 31) * 4;
    bool kAligned = ((K & 7) == 0);

    for (int k0 = 0; k0 < K; k0 += 8) {
        float4 av = make_float4(0.f, 0.f, 0.f, 0.f);
        int gr = brow + arow;
        if (gr < M) {
            if (kAligned) {
                av = *reinterpret_cast<const float4*>(A + (size_t)gr * K + k0 + acol);
            } else {
                float t[4] = {0.f, 0.f, 0.f, 0.f};
#pragma unroll
                for (int q = 0; q < 4; q++) {
                    int kk = k0 + acol + q;
                    if (kk < K) t[q] = A[(size_t)gr * K + kk];
                }
                av = make_float4(t[0], t[1], t[2], t[3]);
            }
        }
        As[acol + 0][arow] = av.x; As[acol + 1][arow] = av.y;
        As[acol + 2][arow] = av.z; As[acol + 3][arow] = av.w;

        float4 wv = make_float4(0.f, 0.f, 0.f, 0.f);
        int gk = k0 + wrow;
        int gc = bcol + wcol;
        if (gk < K) {
            if (gc + 3 < Ncols) {
                wv = *reinterpret_cast<const float4*>(W + (size_t)gk * Ncols + gc);
            } else {
                float t[4] = {0.f, 0.f, 0.f, 0.f};
#pragma unroll
                for (int q = 0; q < 4; q++)
                    if (gc + q < Ncols) t[q] = W[(size_t)gk * Ncols + gc + q];
                wv = make_float4(t[0], t[1], t[2], t[3]);
            }
        }
        *reinterpret_cast<float4*>(&Bs[wrow][wcol]) = wv;
        __syncthreads();

#pragma unroll
        for (int k = 0; k < 8; k++) {
            float4 a0 = *reinterpret_cast<const float4*>(&As[k][tr]);
            float4 a1 = *reinterpret_cast<const float4*>(&As[k][tr + 4]);
            float4 b0 = *reinterpret_cast<const float4*>(&Bs[k][tc]);
            float4 b1 = *reinterpret_cast<const float4*>(&Bs[k][tc + 4]);
            float a[8] = {a0.x, a0.y, a0.z, a0.w, a1.x, a1.y, a1.z, a1.w};
            float b[8] = {b0.x, b0.y, b0.z, b0.w, b1.x, b1.y, b1.z, b1.w};
#pragma unroll
            for (int i = 0; i < 8; i++)
#pragma unroll
                for (int j = 0; j < 8; j++) acc[i][j] += a[i] * b[j];
        }
        __syncthreads();
    }

#pragma unroll
    for (int i = 0; i < 8; i++) {
        int gr = brow + tr + i;
        if (gr >= M) continue;
#pragma unroll
        for (int j = 0; j < 8; j++) {
            int gc = bcol + tc + j;
            if (gc >= Ncols) continue;
            float vv = acc[i][j];
            if (bias) vv += bias[gc];
            if (doRelu) vv = fmaxf(vv, 0.0f);
            C[(size_t)gr * Ncols + gc] = vv;
        }
    }
}

// ---------------- per-node attention coefficients a_s, a_d ----------------------
__global__ void k_att(const float* __restrict__ xh, const float* __restrict__ asrc,
                      const float* __restrict__ adst,
                      float* __restrict__ oas, float* __restrict__ oad) {
    int n = blockIdx.x;
    int h = threadIdx.x >> 5, lane = threadIdx.x & 31;
    const float* xr = xh + (size_t)n * HIDN + h * CH;
    const float* sp = asrc + h * CH;
    const float* dp = adst + h * CH;
    float x0 = xr[lane], x1 = xr[lane + 32];
    float vs = x0 * sp[lane] + x1 * sp[lane + 32];
    float vd = x0 * dp[lane] + x1 * dp[lane + 32];
#pragma unroll
    for (int o = 16; o > 0; o >>= 1) {
        vs += __shfl_xor_sync(0xFFFFFFFFu, vs, o);
        vd += __shfl_xor_sync(0xFFFFFFFFu, vd, o);
    }
    if (lane == 0) { oas[n * NH + h] = vs; oad[n * NH + h] = vd; }
}

// ---------------- edge logits + segment max --------------------------------------
__global__ void k_logits(const int* __restrict__ src, const int* __restrict__ dst,
                         const float* __restrict__ eattr, const float* __restrict__ lattr,
                         const float* __restrict__ v,
                         const float* __restrict__ oas, const float* __restrict__ oad,
                         float* __restrict__ exb, unsigned* __restrict__ mmax) {
    int idx = blockIdx.x * blockDim.x + threadIdx.x;
    if (idx >= EA * NH) return;
    int e = idx >> 2, h = idx & 3;
    int s, d;
    const float* ea;
    if (e < EE) { s = src[e]; d = dst[e]; ea = eattr + (size_t)e * DE; }
    else        { s = d = e - EE;         ea = lattr + (size_t)(e - EE) * DE; }
    float aeV = 0.0f;
#pragma unroll
    for (int j = 0; j < DE; j++) aeV += ea[j] * v[j * NH + h];
    float lg = oas[s * NH + h] + oad[d * NH + h] + aeV;
    lg = (lg > 0.0f) ? lg : NEG * lg;          // leaky_relu
    exb[idx] = lg;
    atomicMax(&mmax[d * NH + h], fenc(lg));
}

// ---------------- exp(logit - max) + segment sum ---------------------------------
__global__ void k_exp(const int* __restrict__ dst, float* __restrict__ exb,
                      const unsigned* __restrict__ mmax, float* __restrict__ denom) {
    int idx = blockIdx.x * blockDim.x + threadIdx.x;
    if (idx >= EA * NH) return;
    int e = idx >> 2, h = idx & 3;
    int d = (e < EE) ? dst[e] : (e - EE);
    float m = fdec(mmax[d * NH + h]);
    float ex = expf(exb[idx] - m);
    exb[idx] = ex;
    atomicAdd(&denom[d * NH + h], ex);
}

// ---------------- weighted scatter aggregation (64 thr/edge, float4 + red.v4) ----
__global__ void k_agg(const int* __restrict__ src, const int* __restrict__ dst,
                      const float* __restrict__ xh, const float* __restrict__ exb,
                      const float* __restrict__ denom, float* __restrict__ agg) {
    int t = blockIdx.x * blockDim.x + threadIdx.x;
    int e = t >> 6;
    if (e >= EA) return;
    int j4 = (t & 63) * 4;
    int s, d;
    if (e < EE) { s = src[e]; d = dst[e]; }
    else        { s = d = e - EE; }
    int h = j4 >> 6;
    float alpha = exb[e * NH + h] / denom[d * NH + h];
    float4 xv = *reinterpret_cast<const float4*>(xh + (size_t)s * HIDN + j4);
    red4(agg + (size_t)d * HIDN + j4,
         xv.x * alpha, xv.y * alpha, xv.z * alpha, xv.w * alpha);
}

// ---------------- batchnorm statistics -------------------------------------------
__global__ void k_bnstats(const float* __restrict__ agg, float* __restrict__ mu,
                          float* __restrict__ sq) {
    int j = threadIdx.x;                // column 0..255
    int r0 = blockIdx.x * 128;
    float s = 0.0f, s2 = 0.0f;
    int rmax = min(128, NN - r0);
    for (int r = 0; r < rmax; r++) {
        float vv = agg[(size_t)(r0 + r) * HIDN + j];
        s += vv; s2 += vv * vv;
    }
    atomicAdd(&mu[j], s);
    atomicAdd(&sq[j], s2);
}

// ---------------- batchnorm apply + relu + residual (in-place, float4) -----------
__global__ void k_bnapply(float* __restrict__ agg, const float* __restrict__ mu,
                          const float* __restrict__ sq, const float* __restrict__ gamma,
                          const float* __restrict__ beta, const float* __restrict__ resid) {
    size_t t = (size_t)blockIdx.x * blockDim.x + threadIdx.x;
    if (t >= (size_t)NN * (HIDN / 4)) return;
    int j = (int)(t & (HIDN / 4 - 1)) * 4;
    size_t idx = (t >> 6) * HIDN + j;          // HIDN/4 = 64 threads per row
    float4 vv = *reinterpret_cast<float4*>(agg + idx);
    float4 gm = *reinterpret_cast<const float4*>(gamma + j);
    float4 bt = *reinterpret_cast<const float4*>(beta + j);
    float4 m4 = *reinterpret_cast<const float4*>(mu + j);
    float4 q4 = *reinterpret_cast<const float4*>(sq + j);
    float4 o;
    {
        float mean = m4.x * (1.0f / NN); float var = q4.x * (1.0f / NN) - mean * mean;
        o.x = fmaxf((vv.x - mean) * rsqrtf(var + BNEPS) * gm.x + bt.x, 0.0f);
        mean = m4.y * (1.0f / NN); var = q4.y * (1.0f / NN) - mean * mean;
        o.y = fmaxf((vv.y - mean) * rsqrtf(var + BNEPS) * gm.y + bt.y, 0.0f);
        mean = m4.z * (1.0f / NN); var = q4.z * (1.0f / NN) - mean * mean;
        o.z = fmaxf((vv.z - mean) * rsqrtf(var + BNEPS) * gm.z + bt.z, 0.0f);
        mean = m4.w * (1.0f / NN); var = q4.w * (1.0f / NN) - mean * mean;
        o.w = fmaxf((vv.w - mean) * rsqrtf(var + BNEPS) * gm.w + bt.w, 0.0f);
    }
    if (resid) {
        float4 rv = *reinterpret_cast<const float4*>(resid + idx);
        o.x += rv.x; o.y += rv.y; o.z += rv.z; o.w += rv.w;
    }
    *reinterpret_cast<float4*>(agg + idx) = o;
}

// ---------------- global mean pool (64 thr/node, float4 + red.v4) ----------------
__global__ void k_pool(const float* __restrict__ h, const int* __restrict__ bidx,
                       float* __restrict__ gsum, float* __restrict__ cnt) {
    int t = blockIdx.x * blockDim.x + threadIdx.x;
    int n = t >> 6;
    if (n >= NN) return;
    int j4 = (t & 63) * 4;
    int b = bidx[n];
    float4 hv = *reinterpret_cast<const float4*>(h + (size_t)n * HIDN + j4);
    red4(gsum + (size_t)b * HIDN + j4, hv.x, hv.y, hv.z, hv.w);
    if ((t & 63) == 0) atomicAdd(&cnt[b], 1.0f);
}

__global__ void k_gfinal(float* __restrict__ gsum, const float* __restrict__ cnt) {
    int t = blockIdx.x * blockDim.x + threadIdx.x;
    if (t >= BB * (HIDN / 4)) return;
    int b = t >> 6;
    float inv = 1.0f / fmaxf(cnt[b], 1.0f);
    float4 v = *reinterpret_cast<float4*>(gsum + (size_t)t * 4);
    v.x *= inv; v.y *= inv; v.z *= inv; v.w *= inv;
    *reinterpret_cast<float4*>(gsum + (size_t)t * 4) = v;
}

// ---------------- final linear [64 -> 1] -----------------------------------------
__global__ void k_pred(const float* __restrict__ z2, const float* __restrict__ W3,
                       const float* __restrict__ b3, float* __restrict__ out) {
    int w = (blockIdx.x * blockDim.x + threadIdx.x) >> 5;
    int lane = threadIdx.x & 31;
    if (w >= BB) return;
    float s = z2[(size_t)w * 64 + lane] * W3[lane] + z2[(size_t)w * 64 + lane + 32] * W3[lane + 32];
#pragma unroll
    for (int o = 16; o > 0; o >>= 1) s += __shfl_xor_sync(0xFFFFFFFFu, s, o);
    if (lane == 0) out[w] = s + b3[0];
}

// ====================================================================================
#define SYM(p, s) do { void* _t; cudaGetSymbolAddress(&_t, s); p = (decltype(p))_t; } while (0)

extern "C" void kernel_launch(void* const* d_in, const int* in_sizes, int n_in,
                              void* d_out, int out_size) {
    // metadata order: x, edge_index, edge_attr, batch_idx, [batch_size], in_W, in_b,
    // gat_W, att_src, att_dst, edge_W, att_edge, gat_b, bn_gamma, bn_beta,
    // p_W1, p_b1, p_W2, p_b2, p_W3, p_b3
    int o = (n_in >= 21) ? 0 : -1;   // robust to the scalar batch_size being dropped
    const float* x        = (const float*)d_in[0];
    const int*   ei       = (const int*)d_in[1];
    const float* eattr    = (const float*)d_in[2];
    const int*   bidx     = (const int*)d_in[3];
    const float* in_W     = (const float*)d_in[5 + o];
    const float* in_b     = (const float*)d_in[6 + o];
    const float* gat_W    = (const float*)d_in[7 + o];
    const float* att_src  = (const float*)d_in[8 + o];
    const float* att_dst  = (const float*)d_in[9 + o];
    const float* edge_W   = (const float*)d_in[10 + o];
    const float* att_edge = (const float*)d_in[11 + o];
    // d_in[12+o] = gat_b: cancels exactly inside BatchNorm (constant shift) -> unused
    const float* bn_g     = (const float*)d_in[13 + o];
    const float* bn_b     = (const float*)d_in[14 + o];
    const float* pW1      = (const float*)d_in[15 + o];
    const float* pb1      = (const float*)d_in[16 + o];
    const float* pW2      = (const float*)d_in[17 + o];
    const float* pb2      = (const float*)d_in[18 + o];
    const float* pW3      = (const float*)d_in[19 + o];
    const float* pb3      = (const float*)d_in[20 + o];
    float* out = (float*)d_out;

    const int* src = ei;
    const int* dst = ei + EE;

    float *bufA, *bufB, *xh, *as_, *ad_, *exb, *den, *deg, *lattr, *v, *mu, *sq, *cnt, *gsum, *z1, *z2;
    unsigned* mmax;
    SYM(bufA, g_bufA); SYM(bufB, g_bufB); SYM(xh, g_xh);
    SYM(as_, g_as);    SYM(ad_, g_ad);   SYM(exb, g_ex);
    SYM(mmax, g_mmax); SYM(den, g_denom);
    SYM(deg, g_deg);   SYM(lattr, g_lattr); SYM(v, g_v);
    SYM(mu, g_mu);     SYM(sq, g_sq);
    SYM(cnt, g_cnt);   SYM(gsum, g_gsum); SYM(z1, g_z1); SYM(z2, g_z2);

    // --- self-loop edge attrs + per-layer edge-attention vectors ---
    cudaMemsetAsync(deg, 0, NN * sizeof(float));
    cudaMemsetAsync(lattr, 0, (size_t)NN * DE * sizeof(float));
    k_loop_accum<<<(EE + 127) / 128, 128>>>(dst, eattr, deg, lattr);
    k_loop_fin<<<(NN * DE + 255) / 256, 256>>>(deg, lattr);
    k_veatt<<<LNUM * DE, 128>>>(edge_W, att_edge, v);

    // --- input projection: h = relu(x @ in_W + in_b) ---
    {
        dim3 grid((HIDN + 127) / 128, (NN + 127) / 128);
        k_sgemm<<<grid, 256>>>(x, in_W, in_b, bufA, NN, DIN, HIDN, 1);
    }

    float* cur = bufA;
    float* nxt = bufB;
    for (int l = 0; l < LNUM; l++) {
        // xh = h @ gat_W[l]
        {
            dim3 grid((HIDN + 127) / 128, (NN + 127) / 128);
            k_sgemm<<<grid, 256>>>(cur, gat_W + (size_t)l * HIDN * HIDN, nullptr, xh,
                                   NN, HIDN, HIDN, 0);
        }
        k_att<<<NN, 128>>>(xh, att_src + (size_t)l * NH * CH, att_dst + (size_t)l * NH * CH,
                           as_, ad_);

        cudaMemsetAsync(mmax, 0, (size_t)NN * NH * sizeof(unsigned));  // 0 < fenc(any float)
        cudaMemsetAsync(den, 0, (size_t)NN * NH * sizeof(float));
        cudaMemsetAsync(nxt, 0, (size_t)NN * HIDN * sizeof(float));

        int tE = (EA * NH + 255) / 256;
        k_logits<<<tE, 256>>>(src, dst, eattr, lattr, v + l * DE * NH, as_, ad_, exb, mmax);
        k_exp<<<tE, 256>>>(dst, exb, mmax, den);
        k_agg<<<(EA * 64 + 255) / 256, 256>>>(src, dst, xh, exb, den, nxt);

        cudaMemsetAsync(mu, 0, HIDN * sizeof(float));
        cudaMemsetAsync(sq, 0, HIDN * sizeof(float));
        k_bnstats<<<(NN + 127) / 128, 256>>>(nxt, mu, sq);
        k_bnapply<<<(int)(((size_t)NN * 64 + 255) / 256), 256>>>(
            nxt, mu, sq, bn_g + l * HIDN, bn_b + l * HIDN, (l > 0) ? cur : nullptr);

        float* t = cur; cur = nxt; nxt = t;
    }

    // --- global mean pool ---
    cudaMemsetAsync(cnt, 0, BB * sizeof(float));
    cudaMemsetAsync(gsum, 0, (size_t)BB * HIDN * sizeof(float));
    k_pool<<<(NN * 64 + 255) / 256, 256>>>(cur, bidx, gsum, cnt);
    k_gfinal<<<(BB * 64 + 255) / 256, 256>>>(gsum, cnt);

    // --- predictor MLP ---
    {
        dim3 g1((128 + 127) / 128, (BB + 127) / 128);
        k_sgemm<<<g1, 256>>>(gsum, pW1, pb1, z1, BB, HIDN, 128, 1);
        dim3 g2((64 + 127) / 128, (BB + 127) / 128);
        k_sgemm<<<g2, 256>>>(z1, pW2, pb2, z2, BB, 128, 64, 1);
    }
    k_pred<<<(BB * 32 + 127) / 128, 128>>>(z2, pW3, pb3, out);
}

// round 10
// speedup vs baseline: 1.8150x; 1.8150x over previous
#include <cuda_runtime.h>
#include <cstdint>

#define NN 150000
#define EE 300000
#define BB 4096
#define DIN 155
#define DE 6
#define HIDN 256
#define LNUM 4
#define NH 4
#define CH 64
#define EA (EE + NN)
#define NEG 0.2f
#define BNEPS 1e-5f

// ---------------- device scratch (static: no allocations allowed) ----------------
__device__ float    g_bufA[(size_t)NN * HIDN];
__device__ float    g_bufB[(size_t)NN * HIDN];
__device__ float    g_xh[(size_t)NN * HIDN];
__device__ float    g_as[NN * NH];
__device__ float    g_ad[NN * NH];
__device__ float    g_ex[(size_t)EA * NH];     // logits, then exp(logits - m) in-place
// combined per-layer scratch zeroed with ONE memset:
// [0, NN*NH)            mmax (unsigned; 0 < fenc(any float))
// [NN*NH, 2*NN*NH)      denom
// [2*NN*NH, +HIDN)      mu
// [2*NN*NH+HIDN, +HIDN) sq
#define SM_MMAX  0
#define SM_DEN   (NN * NH)
#define SM_MU    (2 * NN * NH)
#define SM_SQ    (2 * NN * NH + HIDN)
#define SM_TOTAL (2 * NN * NH + 2 * HIDN)
__device__ float    g_small[SM_TOTAL];
__device__ float    g_deg[NN];
__device__ float    g_lattr[NN * DE];
__device__ float    g_v[LNUM * DE * NH];       // edge_W[l] @ att_edge[l]  -> [DE, NH] per layer
__device__ float    g_cnt[BB];
__device__ float    g_gsum[BB * HIDN];
__device__ float    g_z1[BB * 128];
__device__ float    g_z2[BB * 64];

// monotone float <-> uint encoding for atomicMax over signed floats
__device__ __forceinline__ unsigned fenc(float x) {
    unsigned u = __float_as_uint(x);
    return (u & 0x80000000u) ? ~u : (u | 0x80000000u);
}
__device__ __forceinline__ float fdec(unsigned u) {
    return (u & 0x80000000u) ? __uint_as_float(u & 0x7FFFFFFFu) : __uint_as_float(~u);
}

// vector reduction: one REDG for 4 consecutive floats (sm_90+)
__device__ __forceinline__ void red4(float* addr, float a, float b, float c, float d) {
    asm volatile("red.global.add.v4.f32 [%0], {%1, %2, %3, %4};"
                 :: "l"(addr), "f"(a), "f"(b), "f"(c), "f"(d) : "memory");
}

__device__ __forceinline__ float tf32r(float x) {
    uint32_t r;
    asm("cvt.rna.tf32.f32 %0, %1;" : "=r"(r) : "f"(x));
    return __uint_as_float(r);
}

// ---------------- self-loop attr: deg + sum of incoming edge_attr ----------------
__global__ void k_loop_accum(const int* __restrict__ dst, const float* __restrict__ eattr,
                             float* __restrict__ deg, float* __restrict__ lattr) {
    int e = blockIdx.x * blockDim.x + threadIdx.x;
    if (e >= EE) return;
    int d = dst[e];
    atomicAdd(&deg[d], 1.0f);
#pragma unroll
    for (int j = 0; j < DE; j++) atomicAdd(&lattr[d * DE + j], eattr[(size_t)e * DE + j]);
}

__global__ void k_loop_fin(const float* __restrict__ deg, float* __restrict__ lattr) {
    int idx = blockIdx.x * blockDim.x + threadIdx.x;
    if (idx >= NN * DE) return;
    int n = idx / DE;
    lattr[idx] *= (1.0f / fmaxf(deg[n], 1.0f));
}

// ---------------- v[l][d][h] = sum_c edge_W[l][d][h*64+c] * att_edge[l][h][c] ----
__global__ void k_veatt(const float* __restrict__ edge_W, const float* __restrict__ att_edge,
                        float* __restrict__ v) {
    int l = blockIdx.x / DE, d = blockIdx.x % DE;
    int h = threadIdx.x >> 5, lane = threadIdx.x & 31;
    const float* wp = edge_W + (size_t)l * DE * HIDN + (size_t)d * HIDN + h * CH;
    const float* ap = att_edge + (size_t)l * NH * CH + h * CH;
    float s = wp[lane] * ap[lane] + wp[lane + 32] * ap[lane + 32];
#pragma unroll
    for (int o = 16; o > 0; o >>= 1) s += __shfl_xor_sync(0xFFFFFFFFu, s, o);
    if (lane == 0) v[blockIdx.x * NH + h] = s;
}

// ========== tf32 tensor-core GEMM: C[M,256] = act(A[M,K] @ W[K,256] + bias) ======
// BLOCK 128x128, BK=32, 8 warps (warp tile 32x64), mma.sync.m16n8k8 tf32
// K arbitrary (zero-padded in SMEM); vectorized A-loads only when K%32==0.
__global__ __launch_bounds__(256, 2) void k_tf32gemm(
    const float* __restrict__ A, const float* __restrict__ W,
    const float* __restrict__ bias, float* __restrict__ C,
    int M, int K, int doRelu)
{
    __shared__ float As[128][36];   // [m][k], pad 4 -> conflict-free frag loads
    __shared__ float Bs[32][132];   // [k][n], pad 4

    int tid = threadIdx.x;
    int lane = tid & 31;
    int wid = tid >> 5;
    int wm = (wid & 3) * 32;        // warp row offset in tile
    int wn = (wid >> 2) * 64;       // warp col offset in tile
    int g = lane >> 2;              // groupID (0..7)
    int tg = lane & 3;              // thread-in-group (0..3)
    int brow = blockIdx.y * 128;
    int bcol = blockIdx.x * 128;

    float acc[2][8][4];
#pragma unroll
    for (int mt = 0; mt < 2; mt++)
#pragma unroll
        for (int nt = 0; nt < 8; nt++)
#pragma unroll
            for (int q = 0; q < 4; q++) acc[mt][nt][q] = 0.0f;

    int ar = tid >> 3;             // A load: row 0..31 within 32-row group
    int ac = (tid & 7) * 4;        // A load: col 0..28
    int brr = tid >> 5;            // B load: k-row 0..7 within 8-row group
    int bcc = (tid & 31) * 4;      // B load: col 0..124

    bool vecA = ((K & 31) == 0);   // aligned float4 A-path (K=256); scalar otherwise

    for (int k0 = 0; k0 < K; k0 += 32) {
#pragma unroll
        for (int p = 0; p < 4; p++) {
            int row = p * 32 + ar;
            int gr = brow + row;
            float t0 = 0.f, t1 = 0.f, t2 = 0.f, t3 = 0.f;
            if (gr < M) {
                if (vecA) {
                    float4 v = *reinterpret_cast<const float4*>(A + (size_t)gr * K + k0 + ac);
                    t0 = v.x; t1 = v.y; t2 = v.z; t3 = v.w;
                } else {
                    const float* ap = A + (size_t)gr * K;
                    int kk = k0 + ac;
                    if (kk + 3 < K) {
                        t0 = ap[kk]; t1 = ap[kk + 1]; t2 = ap[kk + 2]; t3 = ap[kk + 3];
                    } else {
                        if (kk     < K) t0 = ap[kk];
                        if (kk + 1 < K) t1 = ap[kk + 1];
                        if (kk + 2 < K) t2 = ap[kk + 2];
                        if (kk + 3 < K) t3 = ap[kk + 3];
                    }
                }
            }
            As[row][ac + 0] = tf32r(t0); As[row][ac + 1] = tf32r(t1);
            As[row][ac + 2] = tf32r(t2); As[row][ac + 3] = tf32r(t3);
        }
#pragma unroll
        for (int p = 0; p < 4; p++) {
            int krow = p * 8 + brr;
            int gk = k0 + krow;
            float4 v = make_float4(0.f, 0.f, 0.f, 0.f);
            if (gk < K) v = *reinterpret_cast<const float4*>(W + (size_t)gk * 256 + bcol + bcc);
            Bs[krow][bcc + 0] = tf32r(v.x); Bs[krow][bcc + 1] = tf32r(v.y);
            Bs[krow][bcc + 2] = tf32r(v.z); Bs[krow][bcc + 3] = tf32r(v.w);
        }
        __syncthreads();

#pragma unroll
        for (int kk = 0; kk < 32; kk += 8) {
            uint32_t a[2][4];
#pragma unroll
            for (int mt = 0; mt < 2; mt++) {
                int rb = wm + mt * 16;
                a[mt][0] = __float_as_uint(As[rb + g][kk + tg]);
                a[mt][1] = __float_as_uint(As[rb + g + 8][kk + tg]);
                a[mt][2] = __float_as_uint(As[rb + g][kk + tg + 4]);
                a[mt][3] = __float_as_uint(As[rb + g + 8][kk + tg + 4]);
            }
#pragma unroll
            for (int nt = 0; nt < 8; nt++) {
                int cb = wn + nt * 8 + g;
                uint32_t b0 = __float_as_uint(Bs[kk + tg][cb]);
                uint32_t b1 = __float_as_uint(Bs[kk + tg + 4][cb]);
#pragma unroll
                for (int mt = 0; mt < 2; mt++) {
                    asm volatile(
                        "mma.sync.aligned.m16n8k8.row.col.f32.tf32.tf32.f32 "
                        "{%0,%1,%2,%3}, {%4,%5,%6,%7}, {%8,%9}, {%0,%1,%2,%3};"
                        : "+f"(acc[mt][nt][0]), "+f"(acc[mt][nt][1]),
                          "+f"(acc[mt][nt][2]), "+f"(acc[mt][nt][3])
                        : "r"(a[mt][0]), "r"(a[mt][1]), "r"(a[mt][2]), "r"(a[mt][3]),
                          "r"(b0), "r"(b1));
                }
            }
        }
        __syncthreads();
    }

#pragma unroll
    for (int mt = 0; mt < 2; mt++) {
#pragma unroll
        for (int nt = 0; nt < 8; nt++) {
            int c = bcol + wn + nt * 8 + 2 * tg;
            float b0 = 0.f, b1 = 0.f;
            if (bias) { b0 = bias[c]; b1 = bias[c + 1]; }
            float v0 = acc[mt][nt][0] + b0, v1 = acc[mt][nt][1] + b1;
            float v2 = acc[mt][nt][2] + b0, v3 = acc[mt][nt][3] + b1;
            if (doRelu) {
                v0 = fmaxf(v0, 0.f); v1 = fmaxf(v1, 0.f);
                v2 = fmaxf(v2, 0.f); v3 = fmaxf(v3, 0.f);
            }
            int r0 = brow + wm + mt * 16 + g;
            if (r0 < M)
                *reinterpret_cast<float2*>(C + (size_t)r0 * 256 + c) = make_float2(v0, v1);
            int r1 = r0 + 8;
            if (r1 < M)
                *reinterpret_cast<float2*>(C + (size_t)r1 * 256 + c) = make_float2(v2, v3);
        }
    }
}

// ---------------- fp32 SGEMM (small MLP-head GEMMs only) -------------------------
__global__ __launch_bounds__(256) void k_sgemm(
    const float* __restrict__ A, const float* __restrict__ W,
    const float* __restrict__ bias, float* __restrict__ C,
    int M, int K, int Ncols, int doRelu)
{
    __shared__ float As[8][128];
    __shared__ float Bs[8][128];
    int tid = threadIdx.x;
    int bcol = blockIdx.x * 128;
    int brow = blockIdx.y * 128;
    int tr = (tid >> 4) * 8;
    int tc = (tid & 15) * 8;
    float acc[8][8];
#pragma unroll
    for (int i = 0; i < 8; i++)
#pragma unroll
        for (int j = 0; j < 8; j++) acc[i][j] = 0.0f;

    int arow = tid >> 1, acol = (tid & 1) * 4;
    int wrow = tid >> 5, wcol = (tid & 31) * 4;
    bool kAligned = ((K & 7) == 0);

    for (int k0 = 0; k0 < K; k0 += 8) {
        float4 av = make_float4(0.f, 0.f, 0.f, 0.f);
        int gr = brow + arow;
        if (gr < M) {
            if (kAligned) {
                av = *reinterpret_cast<const float4*>(A + (size_t)gr * K + k0 + acol);
            } else {
                float t[4] = {0.f, 0.f, 0.f, 0.f};
#pragma unroll
                for (int q = 0; q < 4; q++) {
                    int kk = k0 + acol + q;
                    if (kk < K) t[q] = A[(size_t)gr * K + kk];
                }
                av = make_float4(t[0], t[1], t[2], t[3]);
            }
        }
        As[acol + 0][arow] = av.x; As[acol + 1][arow] = av.y;
        As[acol + 2][arow] = av.z; As[acol + 3][arow] = av.w;

        float4 wv = make_float4(0.f, 0.f, 0.f, 0.f);
        int gk = k0 + wrow;
        int gc = bcol + wcol;
        if (gk < K) {
            if (gc + 3 < Ncols) {
                wv = *reinterpret_cast<const float4*>(W + (size_t)gk * Ncols + gc);
            } else {
                float t[4] = {0.f, 0.f, 0.f, 0.f};
#pragma unroll
                for (int q = 0; q < 4; q++)
                    if (gc + q < Ncols) t[q] = W[(size_t)gk * Ncols + gc + q];
                wv = make_float4(t[0], t[1], t[2], t[3]);
            }
        }
        *reinterpret_cast<float4*>(&Bs[wrow][wcol]) = wv;
        __syncthreads();

#pragma unroll
        for (int k = 0; k < 8; k++) {
            float4 a0 = *reinterpret_cast<const float4*>(&As[k][tr]);
            float4 a1 = *reinterpret_cast<const float4*>(&As[k][tr + 4]);
            float4 b0 = *reinterpret_cast<const float4*>(&Bs[k][tc]);
            float4 b1 = *reinterpret_cast<const float4*>(&Bs[k][tc + 4]);
            float a[8] = {a0.x, a0.y, a0.z, a0.w, a1.x, a1.y, a1.z, a1.w};
            float b[8] = {b0.x, b0.y, b0.z, b0.w, b1.x, b1.y, b1.z, b1.w};
#pragma unroll
            for (int i = 0; i < 8; i++)
#pragma unroll
                for (int j = 0; j < 8; j++) acc[i][j] += a[i] * b[j];
        }
        __syncthreads();
    }

#pragma unroll
    for (int i = 0; i < 8; i++) {
        int gr = brow + tr + i;
        if (gr >= M) continue;
#pragma unroll
        for (int j = 0; j < 8; j++) {
            int gc = bcol + tc + j;
            if (gc >= Ncols) continue;
            float vv = acc[i][j];
            if (bias) vv += bias[gc];
            if (doRelu) vv = fmaxf(vv, 0.0f);
            C[(size_t)gr * Ncols + gc] = vv;
        }
    }
}

// ---------------- per-node attention coefficients a_s, a_d ----------------------
__global__ void k_att(const float* __restrict__ xh, const float* __restrict__ asrc,
                      const float* __restrict__ adst,
                      float* __restrict__ oas, float* __restrict__ oad) {
    int n = blockIdx.x;
    int h = threadIdx.x >> 5, lane = threadIdx.x & 31;
    const float* xr = xh + (size_t)n * HIDN + h * CH;
    const float* sp = asrc + h * CH;
    const float* dp = adst + h * CH;
    float x0 = xr[lane], x1 = xr[lane + 32];
    float vs = x0 * sp[lane] + x1 * sp[lane + 32];
    float vd = x0 * dp[lane] + x1 * dp[lane + 32];
#pragma unroll
    for (int o = 16; o > 0; o >>= 1) {
        vs += __shfl_xor_sync(0xFFFFFFFFu, vs, o);
        vd += __shfl_xor_sync(0xFFFFFFFFu, vd, o);
    }
    if (lane == 0) { oas[n * NH + h] = vs; oad[n * NH + h] = vd; }
}

// ---------------- edge logits + segment max --------------------------------------
__global__ void k_logits(const int* __restrict__ src, const int* __restrict__ dst,
                         const float* __restrict__ eattr, const float* __restrict__ lattr,
                         const float* __restrict__ v,
                         const float* __restrict__ oas, const float* __restrict__ oad,
                         float* __restrict__ exb, unsigned* __restrict__ mmax) {
    int idx = blockIdx.x * blockDim.x + threadIdx.x;
    if (idx >= EA * NH) return;
    int e = idx >> 2, h = idx & 3;
    int s, d;
    const float* ea;
    if (e < EE) { s = src[e]; d = dst[e]; ea = eattr + (size_t)e * DE; }
    else        { s = d = e - EE;         ea = lattr + (size_t)(e - EE) * DE; }
    float aeV = 0.0f;
#pragma unroll
    for (int j = 0; j < DE; j++) aeV += ea[j] * v[j * NH + h];
    float lg = oas[s * NH + h] + oad[d * NH + h] + aeV;
    lg = (lg > 0.0f) ? lg : NEG * lg;          // leaky_relu
    exb[idx] = lg;
    atomicMax(&mmax[d * NH + h], fenc(lg));
}

// ---------------- exp(logit - max) + segment sum ---------------------------------
__global__ void k_exp(const int* __restrict__ dst, float* __restrict__ exb,
                      const unsigned* __restrict__ mmax, float* __restrict__ denom) {
    int idx = blockIdx.x * blockDim.x + threadIdx.x;
    if (idx >= EA * NH) return;
    int e = idx >> 2, h = idx & 3;
    int d = (e < EE) ? dst[e] : (e - EE);
    float m = fdec(mmax[d * NH + h]);
    float ex = expf(exb[idx] - m);
    exb[idx] = ex;
    atomicAdd(&denom[d * NH + h], ex);
}

// ------- self-loop aggregation term: agg[n] = xh[n] * alpha_loop (direct store) ---
// replaces the big memset AND removes self-loop edges from the atomic path
__global__ void k_agginit(const float* __restrict__ xh, const float* __restrict__ exb,
                          const float* __restrict__ denom, float* __restrict__ agg) {
    int t = blockIdx.x * blockDim.x + threadIdx.x;
    int n = t >> 6;
    if (n >= NN) return;
    int j4 = (t & 63) * 4;
    int h = j4 >> 6;
    float alpha = exb[(size_t)(EE + n) * NH + h] / denom[n * NH + h];
    float4 xv = *reinterpret_cast<const float4*>(xh + (size_t)n * HIDN + j4);
    xv.x *= alpha; xv.y *= alpha; xv.z *= alpha; xv.w *= alpha;
    *reinterpret_cast<float4*>(agg + (size_t)n * HIDN + j4) = xv;
}

// ---------------- weighted scatter aggregation (real edges only) -----------------
__global__ void k_agg(const int* __restrict__ src, const int* __restrict__ dst,
                      const float* __restrict__ xh, const float* __restrict__ exb,
                      const float* __restrict__ denom, float* __restrict__ agg) {
    int t = blockIdx.x * blockDim.x + threadIdx.x;
    int e = t >> 6;
    if (e >= EE) return;
    int j4 = (t & 63) * 4;
    int s = src[e], d = dst[e];
    int h = j4 >> 6;
    float alpha = exb[e * NH + h] / denom[d * NH + h];
    float4 xv = *reinterpret_cast<const float4*>(xh + (size_t)s * HIDN + j4);
    red4(agg + (size_t)d * HIDN + j4,
         xv.x * alpha, xv.y * alpha, xv.z * alpha, xv.w * alpha);
}

// ---------------- batchnorm statistics -------------------------------------------
__global__ void k_bnstats(const float* __restrict__ agg, float* __restrict__ mu,
                          float* __restrict__ sq) {
    int j = threadIdx.x;                // column 0..255
    int r0 = blockIdx.x * 128;
    float s = 0.0f, s2 = 0.0f;
    int rmax = min(128, NN - r0);
    for (int r = 0; r < rmax; r++) {
        float vv = agg[(size_t)(r0 + r) * HIDN + j];
        s += vv; s2 += vv * vv;
    }
    atomicAdd(&mu[j], s);
    atomicAdd(&sq[j], s2);
}

// ---------------- batchnorm apply + relu + residual (in-place, float4) -----------
__global__ void k_bnapply(float* __restrict__ agg, const float* __restrict__ mu,
                          const float* __restrict__ sq, const float* __restrict__ gamma,
                          const float* __restrict__ beta, const float* __restrict__ resid) {
    size_t t = (size_t)blockIdx.x * blockDim.x + threadIdx.x;
    if (t >= (size_t)NN * (HIDN / 4)) return;
    int j = (int)(t & (HIDN / 4 - 1)) * 4;
    size_t idx = (t >> 6) * HIDN + j;          // HIDN/4 = 64 threads per row
    float4 vv = *reinterpret_cast<float4*>(agg + idx);
    float4 gm = *reinterpret_cast<const float4*>(gamma + j);
    float4 bt = *reinterpret_cast<const float4*>(beta + j);
    float4 m4 = *reinterpret_cast<const float4*>(mu + j);
    float4 q4 = *reinterpret_cast<const float4*>(sq + j);
    float4 o;
    {
        float mean = m4.x * (1.0f / NN); float var = q4.x * (1.0f / NN) - mean * mean;
        o.x = fmaxf((vv.x - mean) * rsqrtf(var + BNEPS) * gm.x + bt.x, 0.0f);
        mean = m4.y * (1.0f / NN); var = q4.y * (1.0f / NN) - mean * mean;
        o.y = fmaxf((vv.y - mean) * rsqrtf(var + BNEPS) * gm.y + bt.y, 0.0f);
        mean = m4.z * (1.0f / NN); var = q4.z * (1.0f / NN) - mean * mean;
        o.z = fmaxf((vv.z - mean) * rsqrtf(var + BNEPS) * gm.z + bt.z, 0.0f);
        mean = m4.w * (1.0f / NN); var = q4.w * (1.0f / NN) - mean * mean;
        o.w = fmaxf((vv.w - mean) * rsqrtf(var + BNEPS) * gm.w + bt.w, 0.0f);
    }
    if (resid) {
        float4 rv = *reinterpret_cast<const float4*>(resid + idx);
        o.x += rv.x; o.y += rv.y; o.z += rv.z; o.w += rv.w;
    }
    *reinterpret_cast<float4*>(agg + idx) = o;
}

// ---------------- global mean pool (64 thr/node, float4 + red.v4) ----------------
__global__ void k_pool(const float* __restrict__ h, const int* __restrict__ bidx,
                       float* __restrict__ gsum, float* __restrict__ cnt) {
    int t = blockIdx.x * blockDim.x + threadIdx.x;
    int n = t >> 6;
    if (n >= NN) return;
    int j4 = (t & 63) * 4;
    int b = bidx[n];
    float4 hv = *reinterpret_cast<const float4*>(h + (size_t)n * HIDN + j4);
    red4(gsum + (size_t)b * HIDN + j4, hv.x, hv.y, hv.z, hv.w);
    if ((t & 63) == 0) atomicAdd(&cnt[b], 1.0f);
}

__global__ void k_gfinal(float* __restrict__ gsum, const float* __restrict__ cnt) {
    int t = blockIdx.x * blockDim.x + threadIdx.x;
    if (t >= BB * (HIDN / 4)) return;
    int b = t >> 6;
    float inv = 1.0f / fmaxf(cnt[b], 1.0f);
    float4 v = *reinterpret_cast<float4*>(gsum + (size_t)t * 4);
    v.x *= inv; v.y *= inv; v.z *= inv; v.w *= inv;
    *reinterpret_cast<float4*>(gsum + (size_t)t * 4) = v;
}

// ---------------- final linear [64 -> 1] -----------------------------------------
__global__ void k_pred(const float* __restrict__ z2, const float* __restrict__ W3,
                       const float* __restrict__ b3, float* __restrict__ out) {
    int w = (blockIdx.x * blockDim.x + threadIdx.x) >> 5;
    int lane = threadIdx.x & 31;
    if (w >= BB) return;
    float s = z2[(size_t)w * 64 + lane] * W3[lane] + z2[(size_t)w * 64 + lane + 32] * W3[lane + 32];
#pragma unroll
    for (int o = 16; o > 0; o >>= 1) s += __shfl_xor_sync(0xFFFFFFFFu, s, o);
    if (lane == 0) out[w] = s + b3[0];
}

// ====================================================================================
#define SYM(p, s) do { void* _t; cudaGetSymbolAddress(&_t, s); p = (decltype(p))_t; } while (0)

extern "C" void kernel_launch(void* const* d_in, const int* in_sizes, int n_in,
                              void* d_out, int out_size) {
    int o = (n_in >= 21) ? 0 : -1;   // robust to the scalar batch_size being dropped
    const float* x        = (const float*)d_in[0];
    const int*   ei       = (const int*)d_in[1];
    const float* eattr    = (const float*)d_in[2];
    const int*   bidx     = (const int*)d_in[3];
    const float* in_W     = (const float*)d_in[5 + o];
    const float* in_b     = (const float*)d_in[6 + o];
    const float* gat_W    = (const float*)d_in[7 + o];
    const float* att_src  = (const float*)d_in[8 + o];
    const float* att_dst  = (const float*)d_in[9 + o];
    const float* edge_W   = (const float*)d_in[10 + o];
    const float* att_edge = (const float*)d_in[11 + o];
    // d_in[12+o] = gat_b: cancels exactly inside BatchNorm (constant shift) -> unused
    const float* bn_g     = (const float*)d_in[13 + o];
    const float* bn_b     = (const float*)d_in[14 + o];
    const float* pW1      = (const float*)d_in[15 + o];
    const float* pb1      = (const float*)d_in[16 + o];
    const float* pW2      = (const float*)d_in[17 + o];
    const float* pb2      = (const float*)d_in[18 + o];
    const float* pW3      = (const float*)d_in[19 + o];
    const float* pb3      = (const float*)d_in[20 + o];
    float* out = (float*)d_out;

    const int* src = ei;
    const int* dst = ei + EE;

    float *bufA, *bufB, *xh, *as_, *ad_, *exb, *small, *deg, *lattr, *v, *cnt, *gsum, *z1, *z2;
    SYM(bufA, g_bufA); SYM(bufB, g_bufB); SYM(xh, g_xh);
    SYM(as_, g_as);    SYM(ad_, g_ad);   SYM(exb, g_ex);
    SYM(small, g_small);
    SYM(deg, g_deg);   SYM(lattr, g_lattr); SYM(v, g_v);
    SYM(cnt, g_cnt);   SYM(gsum, g_gsum); SYM(z1, g_z1); SYM(z2, g_z2);

    unsigned* mmax = (unsigned*)(small + SM_MMAX);
    float*    den  = small + SM_DEN;
    float*    mu   = small + SM_MU;
    float*    sq   = small + SM_SQ;

    // --- self-loop edge attrs + per-layer edge-attention vectors ---
    cudaMemsetAsync(deg, 0, NN * sizeof(float));
    cudaMemsetAsync(lattr, 0, (size_t)NN * DE * sizeof(float));
    k_loop_accum<<<(EE + 127) / 128, 128>>>(dst, eattr, deg, lattr);
    k_loop_fin<<<(NN * DE + 255) / 256, 256>>>(deg, lattr);
    k_veatt<<<LNUM * DE, 128>>>(edge_W, att_edge, v);

    // --- input projection: h = relu(x @ in_W + in_b)  (tf32, ragged K=155) ---
    {
        dim3 grid(2, (NN + 127) / 128);
        k_tf32gemm<<<grid, 256>>>(x, in_W, in_b, bufA, NN, DIN, 1);
    }

    float* cur = bufA;
    float* nxt = bufB;
    for (int l = 0; l < LNUM; l++) {
        // xh = h @ gat_W[l]  (tf32 tensor cores)
        {
            dim3 grid(2, (NN + 127) / 128);
            k_tf32gemm<<<grid, 256>>>(cur, gat_W + (size_t)l * HIDN * HIDN, nullptr, xh,
                                      NN, HIDN, 0);
        }
        k_att<<<NN, 128>>>(xh, att_src + (size_t)l * NH * CH, att_dst + (size_t)l * NH * CH,
                           as_, ad_);

        // one memset zeroes mmax + denom + mu + sq (0 is identity for all four)
        cudaMemsetAsync(small, 0, SM_TOTAL * sizeof(float));

        int tE = (EA * NH + 255) / 256;
        k_logits<<<tE, 256>>>(src, dst, eattr, lattr, v + l * DE * NH, as_, ad_, exb, mmax);
        k_exp<<<tE, 256>>>(dst, exb, mmax, den);
        k_agginit<<<(NN * 64 + 255) / 256, 256>>>(xh, exb, den, nxt);
        k_agg<<<(EE * 64 + 255) / 256, 256>>>(src, dst, xh, exb, den, nxt);

        k_bnstats<<<(NN + 127) / 128, 256>>>(nxt, mu, sq);
        k_bnapply<<<(int)(((size_t)NN * 64 + 255) / 256), 256>>>(
            nxt, mu, sq, bn_g + l * HIDN, bn_b + l * HIDN, (l > 0) ? cur : nullptr);

        float* t = cur; cur = nxt; nxt = t;
    }

    // --- global mean pool ---
    cudaMemsetAsync(cnt, 0, BB * sizeof(float));
    cudaMemsetAsync(gsum, 0, (size_t)BB * HIDN * sizeof(float));
    k_pool<<<(NN * 64 + 255) / 256, 256>>>(cur, bidx, gsum, cnt);
    k_gfinal<<<(BB * 64 + 255) / 256, 256>>>(gsum, cnt);

    // --- predictor MLP ---
    {
        dim3 g1((128 + 127) / 128, (BB + 127) / 128);
        k_sgemm<<<g1, 256>>>(gsum, pW1, pb1, z1, BB, HIDN, 128, 1);
        dim3 g2((64 + 127) / 128, (BB + 127) / 128);
        k_sgemm<<<g2, 256>>>(z1, pW2, pb2, z2, BB, 128, 64, 1);
    }
    k_pred<<<(BB * 32 + 127) / 128, 128>>>(z2, pW3, pb3, out);
}

// round 12
// speedup vs baseline: 2.1185x; 1.1672x over previous
#include <cuda_runtime.h>
#include <cstdint>

#define NN 150000
#define EE 300000
#define BB 4096
#define DIN 155
#define DE 6
#define HIDN 256
#define LNUM 4
#define NH 4
#define CH 64
#define EA (EE + NN)
#define NEG 0.2f
#define BNEPS 1e-5f
#define NBLK_SCAN 586                  // 586*256 = 150016 >= NN

// ---------------- device scratch (static: no allocations allowed) ----------------
__device__ float    g_bufA[(size_t)NN * HIDN];
__device__ float    g_bufB[(size_t)NN * HIDN];
__device__ float    g_xh[(size_t)NN * HIDN];
__device__ float    g_as[NN * NH];
__device__ float    g_ad[NN * NH];
__device__ float    g_ex[(size_t)EA * NH];
// combined per-layer scratch zeroed with ONE memset (0 is identity for all four)
#define SM_MMAX  0
#define SM_DEN   (NN * NH)
#define SM_MU    (2 * NN * NH)
#define SM_SQ    (2 * NN * NH + HIDN)
#define SM_TOTAL (2 * NN * NH + 2 * HIDN)
__device__ float    g_small[SM_TOTAL];
__device__ float    g_deg[NN];
__device__ float    g_lattr[NN * DE];
__device__ float    g_v[LNUM * DE * NH];
__device__ float    g_cnt[BB];
__device__ float    g_gsum[BB * HIDN];
__device__ float    g_z1[BB * 128];
__device__ float    g_z2[BB * 64];
// CSR (built once, reused 4 layers)
__device__ int      g_degi[NN];
__device__ int      g_roff[NN + 1];
__device__ int      g_cur[NN];
__device__ int      g_eidx[EE];
__device__ int      g_bsum[1024];

__device__ __forceinline__ unsigned fenc(float x) {
    unsigned u = __float_as_uint(x);
    return (u & 0x80000000u) ? ~u : (u | 0x80000000u);
}
__device__ __forceinline__ float fdec(unsigned u) {
    return (u & 0x80000000u) ? __uint_as_float(u & 0x7FFFFFFFu) : __uint_as_float(~u);
}
__device__ __forceinline__ float tf32r(float x) {
    uint32_t r;
    asm("cvt.rna.tf32.f32 %0, %1;" : "=r"(r) : "f"(x));
    return __uint_as_float(r);
}
__device__ __forceinline__ uint32_t tf32u(float x) {
    uint32_t r;
    asm("cvt.rna.tf32.f32 %0, %1;" : "=r"(r) : "f"(x));
    return r;
}
__device__ __forceinline__ uint32_t smem_u32(const void* p) {
    uint32_t a;
    asm("{ .reg .u64 t; cvta.to.shared.u64 t, %1; cvt.u32.u64 %0, t; }" : "=r"(a) : "l"(p));
    return a;
}
__device__ __forceinline__ void cp16(uint32_t dst, const float* src) {
    asm volatile("cp.async.cg.shared.global [%0], [%1], 16;" :: "r"(dst), "l"(src));
}

// ---------------- self-loop attr: deg(+int) + sum of incoming edge_attr ----------
__global__ void k_loop_accum(const int* __restrict__ dst, const float* __restrict__ eattr,
                             float* __restrict__ deg, float* __restrict__ lattr,
                             int* __restrict__ degi) {
    int e = blockIdx.x * blockDim.x + threadIdx.x;
    if (e >= EE) return;
    int d = dst[e];
    atomicAdd(&deg[d], 1.0f);
    atomicAdd(&degi[d], 1);
#pragma unroll
    for (int j = 0; j < DE; j++) atomicAdd(&lattr[d * DE + j], eattr[(size_t)e * DE + j]);
}

__global__ void k_loop_fin(const float* __restrict__ deg, float* __restrict__ lattr) {
    int idx = blockIdx.x * blockDim.x + threadIdx.x;
    if (idx >= NN * DE) return;
    int n = idx / DE;
    lattr[idx] *= (1.0f / fmaxf(deg[n], 1.0f));
}

// ---------------- CSR build: 3-kernel exclusive scan + counting fill -------------
__global__ void k_scan1(const int* __restrict__ degi, int* __restrict__ roff,
                        int* __restrict__ bsum) {
    __shared__ int ws[8];
    int i = blockIdx.x * 256 + threadIdx.x;
    int v = (i < NN) ? degi[i] : 0;
    int x = v;
#pragma unroll
    for (int o = 1; o < 32; o <<= 1) {
        int y = __shfl_up_sync(0xFFFFFFFFu, x, o);
        if ((threadIdx.x & 31) >= o) x += y;
    }
    if ((threadIdx.x & 31) == 31) ws[threadIdx.x >> 5] = x;
    __syncthreads();
    if (threadIdx.x < 8) {
        int y = ws[threadIdx.x];
#pragma unroll
        for (int o = 1; o < 8; o <<= 1) {
            int z = __shfl_up_sync(0xFFu, y, o);
            if (threadIdx.x >= o) y += z;
        }
        ws[threadIdx.x] = y;
    }
    __syncthreads();
    int base = (threadIdx.x >= 32) ? ws[(threadIdx.x >> 5) - 1] : 0;
    int incl = x + base;
    if (i < NN) roff[i] = incl - v;               // exclusive within block
    if (threadIdx.x == 255) bsum[blockIdx.x] = incl;
}

__global__ void k_scan2(int* __restrict__ bsum, int nb) {
    __shared__ int ws[32];
    int tid = threadIdx.x;
    int v = (tid < nb) ? bsum[tid] : 0;
    int x = v;
#pragma unroll
    for (int o = 1; o < 32; o <<= 1) {
        int y = __shfl_up_sync(0xFFFFFFFFu, x, o);
        if ((tid & 31) >= o) x += y;
    }
    if ((tid & 31) == 31) ws[tid >> 5] = x;
    __syncthreads();
    if (tid < 32) {
        int y = ws[tid];
#pragma unroll
        for (int o = 1; o < 32; o <<= 1) {
            int z = __shfl_up_sync(0xFFFFFFFFu, y, o);
            if (tid >= o) y += z;
        }
        ws[tid] = y;
    }
    __syncthreads();
    int base = (tid >= 32) ? ws[(tid >> 5) - 1] : 0;
    if (tid < nb) bsum[tid] = x + base - v;       // exclusive block offsets (in place)
}

__global__ void k_scan3(int* __restrict__ roff, const int* __restrict__ bsum) {
    int i = blockIdx.x * 256 + threadIdx.x;
    if (i < NN) roff[i] += bsum[blockIdx.x];
    if (i == 0) roff[NN] = EE;
}

__global__ void k_copyoff(const int* __restrict__ roff, int* __restrict__ cur) {
    int i = blockIdx.x * blockDim.x + threadIdx.x;
    if (i < NN) cur[i] = roff[i];
}

__global__ void k_fillcsr(const int* __restrict__ dst, int* __restrict__ cur,
                          int* __restrict__ eidx) {
    int e = blockIdx.x * blockDim.x + threadIdx.x;
    if (e >= EE) return;
    int p = atomicAdd(&cur[dst[e]], 1);
    eidx[p] = e;
}

// ---------------- v[l][d][h] = sum_c edge_W[l][d][h*64+c] * att_edge[l][h][c] ----
__global__ void k_veatt(const float* __restrict__ edge_W, const float* __restrict__ att_edge,
                        float* __restrict__ v) {
    int l = blockIdx.x / DE, d = blockIdx.x % DE;
    int h = threadIdx.x >> 5, lane = threadIdx.x & 31;
    const float* wp = edge_W + (size_t)l * DE * HIDN + (size_t)d * HIDN + h * CH;
    const float* ap = att_edge + (size_t)l * NH * CH + h * CH;
    float s = wp[lane] * ap[lane] + wp[lane + 32] * ap[lane + 32];
#pragma unroll
    for (int o = 16; o > 0; o >>= 1) s += __shfl_xor_sync(0xFFFFFFFFu, s, o);
    if (lane == 0) v[blockIdx.x * NH + h] = s;
}

// ===== cp.async double-buffered tf32 GEMM, K=256 fixed: C = A[M,256] @ W[256,256]
#define AS_ELEMS (128 * 36)
#define BS_ELEMS (32 * 132)
#define G256_SMEM ((2 * AS_ELEMS + 2 * BS_ELEMS) * 4)

__global__ __launch_bounds__(256, 2) void k_gemm256(
    const float* __restrict__ A, const float* __restrict__ W,
    float* __restrict__ C, int M)
{
    extern __shared__ float sm[];
    float* Asm = sm;                       // [2][128][36]
    float* Bsm = sm + 2 * AS_ELEMS;        // [2][32][132]
    uint32_t aBase = smem_u32(Asm);
    uint32_t bBase = smem_u32(Bsm);

    int tid = threadIdx.x;
    int lane = tid & 31;
    int wid = tid >> 5;
    int wm = (wid & 3) * 32;
    int wn = (wid >> 2) * 64;
    int g = lane >> 2;
    int tg = lane & 3;
    int brow = blockIdx.y * 128;
    int bcol = blockIdx.x * 128;

    int ar = tid >> 3, ac = (tid & 7) * 4;     // A: 4 chunks of 32 rows
    int brr = tid >> 5, bcc = (tid & 31) * 4;  // B: 4 chunks of 8 k-rows

    float acc[2][8][4];
#pragma unroll
    for (int mt = 0; mt < 2; mt++)
#pragma unroll
        for (int nt = 0; nt < 8; nt++)
#pragma unroll
            for (int q = 0; q < 4; q++) acc[mt][nt][q] = 0.0f;

#define G256_ISSUE(ST, K0)                                                          \
    do {                                                                            \
        _Pragma("unroll")                                                           \
        for (int p = 0; p < 4; p++) {                                               \
            int row = p * 32 + ar; int gr = brow + row;                             \
            if (gr < M)                                                             \
                cp16(aBase + (uint32_t)(((ST) * AS_ELEMS + row * 36 + ac) * 4),     \
                     A + (size_t)gr * 256 + (K0) + ac);                             \
        }                                                                           \
        _Pragma("unroll")                                                           \
        for (int p = 0; p < 4; p++) {                                               \
            int kr = p * 8 + brr;                                                   \
            cp16(bBase + (uint32_t)(((ST) * BS_ELEMS + kr * 132 + bcc) * 4),        \
                 W + (size_t)((K0) + kr) * 256 + bcol + bcc);                       \
        }                                                                           \
        asm volatile("cp.async.commit_group;");                                     \
    } while (0)

    G256_ISSUE(0, 0);

#pragma unroll
    for (int it = 0; it < 8; it++) {
        if (it < 7) {
            G256_ISSUE((it + 1) & 1, (it + 1) * 32);
            asm volatile("cp.async.wait_group 1;");
        } else {
            asm volatile("cp.async.wait_group 0;");
        }
        __syncthreads();
        const float* Ab = Asm + (it & 1) * AS_ELEMS;
        const float* Bb = Bsm + (it & 1) * BS_ELEMS;
#pragma unroll
        for (int kk = 0; kk < 32; kk += 8) {
            uint32_t a[2][4];
#pragma unroll
            for (int mt = 0; mt < 2; mt++) {
                int rb = wm + mt * 16;
                a[mt][0] = tf32u(Ab[(rb + g) * 36 + kk + tg]);
                a[mt][1] = tf32u(Ab[(rb + g + 8) * 36 + kk + tg]);
                a[mt][2] = tf32u(Ab[(rb + g) * 36 + kk + tg + 4]);
                a[mt][3] = tf32u(Ab[(rb + g + 8) * 36 + kk + tg + 4]);
            }
#pragma unroll
            for (int nt = 0; nt < 8; nt++) {
                int cb = wn + nt * 8 + g;
                uint32_t b0 = tf32u(Bb[(kk + tg) * 132 + cb]);
                uint32_t b1 = tf32u(Bb[(kk + tg + 4) * 132 + cb]);
#pragma unroll
                for (int mt = 0; mt < 2; mt++) {
                    asm volatile(
                        "mma.sync.aligned.m16n8k8.row.col.f32.tf32.tf32.f32 "
                        "{%0,%1,%2,%3}, {%4,%5,%6,%7}, {%8,%9}, {%0,%1,%2,%3};"
                        : "+f"(acc[mt][nt][0]), "+f"(acc[mt][nt][1]),
                          "+f"(acc[mt][nt][2]), "+f"(acc[mt][nt][3])
                        : "r"(a[mt][0]), "r"(a[mt][1]), "r"(a[mt][2]), "r"(a[mt][3]),
                          "r"(b0), "r"(b1));
                }
            }
        }
        __syncthreads();
    }

#pragma unroll
    for (int mt = 0; mt < 2; mt++) {
#pragma unroll
        for (int nt = 0; nt < 8; nt++) {
            int c = bcol + wn + nt * 8 + 2 * tg;
            int r0 = brow + wm + mt * 16 + g;
            if (r0 < M)
                *reinterpret_cast<float2*>(C + (size_t)r0 * 256 + c) =
                    make_float2(acc[mt][nt][0], acc[mt][nt][1]);
            int r1 = r0 + 8;
            if (r1 < M)
                *reinterpret_cast<float2*>(C + (size_t)r1 * 256 + c) =
                    make_float2(acc[mt][nt][2], acc[mt][nt][3]);
        }
    }
}

// ========== tf32 GEMM (single-stage, arbitrary K): in-proj only ==================
__global__ __launch_bounds__(256, 2) void k_tf32gemm(
    const float* __restrict__ A, const float* __restrict__ W,
    const float* __restrict__ bias, float* __restrict__ C,
    int M, int K, int doRelu)
{
    __shared__ float As[128][36];
    __shared__ float Bs[32][132];
    int tid = threadIdx.x;
    int lane = tid & 31;
    int wid = tid >> 5;
    int wm = (wid & 3) * 32;
    int wn = (wid >> 2) * 64;
    int g = lane >> 2;
    int tg = lane & 3;
    int brow = blockIdx.y * 128;
    int bcol = blockIdx.x * 128;

    float acc[2][8][4];
#pragma unroll
    for (int mt = 0; mt < 2; mt++)
#pragma unroll
        for (int nt = 0; nt < 8; nt++)
#pragma unroll
            for (int q = 0; q < 4; q++) acc[mt][nt][q] = 0.0f;

    int ar = tid >> 3, ac = (tid & 7) * 4;
    int brr = tid >> 5, bcc = (tid & 31) * 4;
    bool vecA = ((K & 31) == 0);

    for (int k0 = 0; k0 < K; k0 += 32) {
#pragma unroll
        for (int p = 0; p < 4; p++) {
            int row = p * 32 + ar;
            int gr = brow + row;
            float t0 = 0.f, t1 = 0.f, t2 = 0.f, t3 = 0.f;
            if (gr < M) {
                if (vecA) {
                    float4 v = *reinterpret_cast<const float4*>(A + (size_t)gr * K + k0 + ac);
                    t0 = v.x; t1 = v.y; t2 = v.z; t3 = v.w;
                } else {
                    const float* ap = A + (size_t)gr * K;
                    int kk = k0 + ac;
                    if (kk + 3 < K) {
                        t0 = ap[kk]; t1 = ap[kk + 1]; t2 = ap[kk + 2]; t3 = ap[kk + 3];
                    } else {
                        if (kk     < K) t0 = ap[kk];
                        if (kk + 1 < K) t1 = ap[kk + 1];
                        if (kk + 2 < K) t2 = ap[kk + 2];
                        if (kk + 3 < K) t3 = ap[kk + 3];
                    }
                }
            }
            As[row][ac + 0] = tf32r(t0); As[row][ac + 1] = tf32r(t1);
            As[row][ac + 2] = tf32r(t2); As[row][ac + 3] = tf32r(t3);
        }
#pragma unroll
        for (int p = 0; p < 4; p++) {
            int krow = p * 8 + brr;
            int gk = k0 + krow;
            float4 v = make_float4(0.f, 0.f, 0.f, 0.f);
            if (gk < K) v = *reinterpret_cast<const float4*>(W + (size_t)gk * 256 + bcol + bcc);
            Bs[krow][bcc + 0] = tf32r(v.x); Bs[krow][bcc + 1] = tf32r(v.y);
            Bs[krow][bcc + 2] = tf32r(v.z); Bs[krow][bcc + 3] = tf32r(v.w);
        }
        __syncthreads();
#pragma unroll
        for (int kk = 0; kk < 32; kk += 8) {
            uint32_t a[2][4];
#pragma unroll
            for (int mt = 0; mt < 2; mt++) {
                int rb = wm + mt * 16;
                a[mt][0] = __float_as_uint(As[rb + g][kk + tg]);
                a[mt][1] = __float_as_uint(As[rb + g + 8][kk + tg]);
                a[mt][2] = __float_as_uint(As[rb + g][kk + tg + 4]);
                a[mt][3] = __float_as_uint(As[rb + g + 8][kk + tg + 4]);
            }
#pragma unroll
            for (int nt = 0; nt < 8; nt++) {
                int cb = wn + nt * 8 + g;
                uint32_t b0 = __float_as_uint(Bs[kk + tg][cb]);
                uint32_t b1 = __float_as_uint(Bs[kk + tg + 4][cb]);
#pragma unroll
                for (int mt = 0; mt < 2; mt++) {
                    asm volatile(
                        "mma.sync.aligned.m16n8k8.row.col.f32.tf32.tf32.f32 "
                        "{%0,%1,%2,%3}, {%4,%5,%6,%7}, {%8,%9}, {%0,%1,%2,%3};"
                        : "+f"(acc[mt][nt][0]), "+f"(acc[mt][nt][1]),
                          "+f"(acc[mt][nt][2]), "+f"(acc[mt][nt][3])
                        : "r"(a[mt][0]), "r"(a[mt][1]), "r"(a[mt][2]), "r"(a[mt][3]),
                          "r"(b0), "r"(b1));
                }
            }
        }
        __syncthreads();
    }

#pragma unroll
    for (int mt = 0; mt < 2; mt++) {
#pragma unroll
        for (int nt = 0; nt < 8; nt++) {
            int c = bcol + wn + nt * 8 + 2 * tg;
            float b0 = 0.f, b1 = 0.f;
            if (bias) { b0 = bias[c]; b1 = bias[c + 1]; }
            float v0 = acc[mt][nt][0] + b0, v1 = acc[mt][nt][1] + b1;
            float v2 = acc[mt][nt][2] + b0, v3 = acc[mt][nt][3] + b1;
            if (doRelu) {
                v0 = fmaxf(v0, 0.f); v1 = fmaxf(v1, 0.f);
                v2 = fmaxf(v2, 0.f); v3 = fmaxf(v3, 0.f);
            }
            int r0 = brow + wm + mt * 16 + g;
            if (r0 < M)
                *reinterpret_cast<float2*>(C + (size_t)r0 * 256 + c) = make_float2(v0, v1);
            int r1 = r0 + 8;
            if (r1 < M)
                *reinterpret_cast<float2*>(C + (size_t)r1 * 256 + c) = make_float2(v2, v3);
        }
    }
}

// ---------------- fp32 SGEMM (small MLP-head GEMMs only) -------------------------
__global__ __launch_bounds__(256) void k_sgemm(
    const float* __restrict__ A, const float* __restrict__ W,
    const float* __restrict__ bias, float* __restrict__ C,
    int M, int K, int Ncols, int doRelu)
{
    __shared__ float As[8][128];
    __shared__ float Bs[8][128];
    int tid = threadIdx.x;
    int bcol = blockIdx.x * 128;
    int brow = blockIdx.y * 128;
    int tr = (tid >> 4) * 8;
    int tc = (tid & 15) * 8;
    float acc[8][8];
#pragma unroll
    for (int i = 0; i < 8; i++)
#pragma unroll
        for (int j = 0; j < 8; j++) acc[i][j] = 0.0f;

    int arow = tid >> 1, acol = (tid & 1) * 4;
    int wrow = tid >> 5, wcol = (tid & 31) * 4;
    bool kAligned = ((K & 7) == 0);

    for (int k0 = 0; k0 < K; k0 += 8) {
        float4 av = make_float4(0.f, 0.f, 0.f, 0.f);
        int gr = brow + arow;
        if (gr < M) {
            if (kAligned) {
                av = *reinterpret_cast<const float4*>(A + (size_t)gr * K + k0 + acol);
            } else {
                float t[4] = {0.f, 0.f, 0.f, 0.f};
#pragma unroll
                for (int q = 0; q < 4; q++) {
                    int kk = k0 + acol + q;
                    if (kk < K) t[q] = A[(size_t)gr * K + kk];
                }
                av = make_float4(t[0], t[1], t[2], t[3]);
            }
        }
        As[acol + 0][arow] = av.x; As[acol + 1][arow] = av.y;
        As[acol + 2][arow] = av.z; As[acol + 3][arow] = av.w;

        float4 wv = make_float4(0.f, 0.f, 0.f, 0.f);
        int gk = k0 + wrow;
        int gc = bcol + wcol;
        if (gk < K) {
            if (gc + 3 < Ncols) {
                wv = *reinterpret_cast<const float4*>(W + (size_t)gk * Ncols + gc);
            } else {
                float t[4] = {0.f, 0.f, 0.f, 0.f};
#pragma unroll
                for (int q = 0; q < 4; q++)
                    if (gc + q < Ncols) t[q] = W[(size_t)gk * Ncols + gc + q];
                wv = make_float4(t[0], t[1], t[2], t[3]);
            }
        }
        *reinterpret_cast<float4*>(&Bs[wrow][wcol]) = wv;
        __syncthreads();

#pragma unroll
        for (int k = 0; k < 8; k++) {
            float4 a0 = *reinterpret_cast<const float4*>(&As[k][tr]);
            float4 a1 = *reinterpret_cast<const float4*>(&As[k][tr + 4]);
            float4 b0 = *reinterpret_cast<const float4*>(&Bs[k][tc]);
            float4 b1 = *reinterpret_cast<const float4*>(&Bs[k][tc + 4]);
            float a[8] = {a0.x, a0.y, a0.z, a0.w, a1.x, a1.y, a1.z, a1.w};
            float b[8] = {b0.x, b0.y, b0.z, b0.w, b1.x, b1.y, b1.z, b1.w};
#pragma unroll
            for (int i = 0; i < 8; i++)
#pragma unroll
                for (int j = 0; j < 8; j++) acc[i][j] += a[i] * b[j];
        }
        __syncthreads();
    }

#pragma unroll
    for (int i = 0; i < 8; i++) {
        int gr = brow + tr + i;
        if (gr >= M) continue;
#pragma unroll
        for (int j = 0; j < 8; j++) {
            int gc = bcol + tc + j;
            if (gc >= Ncols) continue;
            float vv = acc[i][j];
            if (bias) vv += bias[gc];
            if (doRelu) vv = fmaxf(vv, 0.0f);
            C[(size_t)gr * Ncols + gc] = vv;
        }
    }
}

// ---------------- per-node attention coefficients a_s, a_d ----------------------
__global__ void k_att(const float* __restrict__ xh, const float* __restrict__ asrc,
                      const float* __restrict__ adst,
                      float* __restrict__ oas, float* __restrict__ oad) {
    int n = blockIdx.x;
    int h = threadIdx.x >> 5, lane = threadIdx.x & 31;
    const float* xr = xh + (size_t)n * HIDN + h * CH;
    const float* sp = asrc + h * CH;
    const float* dp = adst + h * CH;
    float x0 = xr[lane], x1 = xr[lane + 32];
    float vs = x0 * sp[lane] + x1 * sp[lane + 32];
    float vd = x0 * dp[lane] + x1 * dp[lane + 32];
#pragma unroll
    for (int o = 16; o > 0; o >>= 1) {
        vs += __shfl_xor_sync(0xFFFFFFFFu, vs, o);
        vd += __shfl_xor_sync(0xFFFFFFFFu, vd, o);
    }
    if (lane == 0) { oas[n * NH + h] = vs; oad[n * NH + h] = vd; }
}

// ---------------- edge logits + segment max --------------------------------------
__global__ void k_logits(const int* __restrict__ src, const int* __restrict__ dst,
                         const float* __restrict__ eattr, const float* __restrict__ lattr,
                         const float* __restrict__ v,
                         const float* __restrict__ oas, const float* __restrict__ oad,
                         float* __restrict__ exb, unsigned* __restrict__ mmax) {
    int idx = blockIdx.x * blockDim.x + threadIdx.x;
    if (idx >= EA * NH) return;
    int e = idx >> 2, h = idx & 3;
    int s, d;
    const float* ea;
    if (e < EE) { s = src[e]; d = dst[e]; ea = eattr + (size_t)e * DE; }
    else        { s = d = e - EE;         ea = lattr + (size_t)(e - EE) * DE; }
    float aeV = 0.0f;
#pragma unroll
    for (int j = 0; j < DE; j++) aeV += ea[j] * v[j * NH + h];
    float lg = oas[s * NH + h] + oad[d * NH + h] + aeV;
    lg = (lg > 0.0f) ? lg : NEG * lg;
    exb[idx] = lg;
    atomicMax(&mmax[d * NH + h], fenc(lg));
}

// ---------------- exp(logit - max) + segment sum ---------------------------------
__global__ void k_exp(const int* __restrict__ dst, float* __restrict__ exb,
                      const unsigned* __restrict__ mmax, float* __restrict__ denom) {
    int idx = blockIdx.x * blockDim.x + threadIdx.x;
    if (idx >= EA * NH) return;
    int e = idx >> 2, h = idx & 3;
    int d = (e < EE) ? dst[e] : (e - EE);
    float m = fdec(mmax[d * NH + h]);
    float ex = expf(exb[idx] - m);
    exb[idx] = ex;
    atomicAdd(&denom[d * NH + h], ex);
}

// --------- CSR aggregation: per-dst gather, registers, ONE direct store ----------
__global__ void k_aggcsr(const int* __restrict__ src, const int* __restrict__ roff,
                         const int* __restrict__ eidx, const float* __restrict__ xh,
                         const float* __restrict__ exb, const float* __restrict__ denom,
                         float* __restrict__ agg) {
    int t = blockIdx.x * blockDim.x + threadIdx.x;
    int n = t >> 6;
    if (n >= NN) return;
    int q = t & 63;
    int j4 = q * 4;
    int h = q >> 4;
    float inv = 1.0f / denom[n * NH + h];
    float exl = exb[(size_t)(EE + n) * NH + h];
    float4 xv = *reinterpret_cast<const float4*>(xh + (size_t)n * HIDN + j4);
    float4 acc = make_float4(exl * xv.x, exl * xv.y, exl * xv.z, exl * xv.w);
    int b0 = roff[n], b1 = roff[n + 1];
    for (int k = b0; k < b1; k++) {
        int e = eidx[k];
        int s = src[e];
        float ev = exb[(size_t)e * NH + h];
        float4 sv = *reinterpret_cast<const float4*>(xh + (size_t)s * HIDN + j4);
        acc.x += ev * sv.x; acc.y += ev * sv.y;
        acc.z += ev * sv.z; acc.w += ev * sv.w;
    }
    acc.x *= inv; acc.y *= inv; acc.z *= inv; acc.w *= inv;
    *reinterpret_cast<float4*>(agg + (size_t)n * HIDN + j4) = acc;
}

// ---------------- batchnorm statistics -------------------------------------------
__global__ void k_bnstats(const float* __restrict__ agg, float* __restrict__ mu,
                          float* __restrict__ sq) {
    int j = threadIdx.x;
    int r0 = blockIdx.x * 128;
    float s = 0.0f, s2 = 0.0f;
    int rmax = min(128, NN - r0);
    for (int r = 0; r < rmax; r++) {
        float vv = agg[(size_t)(r0 + r) * HIDN + j];
        s += vv; s2 += vv * vv;
    }
    atomicAdd(&mu[j], s);
    atomicAdd(&sq[j], s2);
}

// ---------------- batchnorm apply + relu + residual (in-place, float4) -----------
__global__ void k_bnapply(float* __restrict__ agg, const float* __restrict__ mu,
                          const float* __restrict__ sq, const float* __restrict__ gamma,
                          const float* __restrict__ beta, const float* __restrict__ resid) {
    size_t t = (size_t)blockIdx.x * blockDim.x + threadIdx.x;
    if (t >= (size_t)NN * (HIDN / 4)) return;
    int j = (int)(t & (HIDN / 4 - 1)) * 4;
    size_t idx = (t >> 6) * HIDN + j;
    float4 vv = *reinterpret_cast<float4*>(agg + idx);
    float4 gm = *reinterpret_cast<const float4*>(gamma + j);
    float4 bt = *reinterpret_cast<const float4*>(beta + j);
    float4 m4 = *reinterpret_cast<const float4*>(mu + j);
    float4 q4 = *reinterpret_cast<const float4*>(sq + j);
    float4 o;
    {
        float mean = m4.x * (1.0f / NN); float var = q4.x * (1.0f / NN) - mean * mean;
        o.x = fmaxf((vv.x - mean) * rsqrtf(var + BNEPS) * gm.x + bt.x, 0.0f);
        mean = m4.y * (1.0f / NN); var = q4.y * (1.0f / NN) - mean * mean;
        o.y = fmaxf((vv.y - mean) * rsqrtf(var + BNEPS) * gm.y + bt.y, 0.0f);
        mean = m4.z * (1.0f / NN); var = q4.z * (1.0f / NN) - mean * mean;
        o.z = fmaxf((vv.z - mean) * rsqrtf(var + BNEPS) * gm.z + bt.z, 0.0f);
        mean = m4.w * (1.0f / NN); var = q4.w * (1.0f / NN) - mean * mean;
        o.w = fmaxf((vv.w - mean) * rsqrtf(var + BNEPS) * gm.w + bt.w, 0.0f);
    }
    if (resid) {
        float4 rv = *reinterpret_cast<const float4*>(resid + idx);
        o.x += rv.x; o.y += rv.y; o.z += rv.z; o.w += rv.w;
    }
    *reinterpret_cast<float4*>(agg + idx) = o;
}

// ---------------- global mean pool (64 thr/node, float4 + red.v4) ----------------
__device__ __forceinline__ void red4(float* addr, float a, float b, float c, float d) {
    asm volatile("red.global.add.v4.f32 [%0], {%1, %2, %3, %4};"
                 :: "l"(addr), "f"(a), "f"(b), "f"(c), "f"(d) : "memory");
}

__global__ void k_pool(const float* __restrict__ h, const int* __restrict__ bidx,
                       float* __restrict__ gsum, float* __restrict__ cnt) {
    int t = blockIdx.x * blockDim.x + threadIdx.x;
    int n = t >> 6;
    if (n >= NN) return;
    int j4 = (t & 63) * 4;
    int b = bidx[n];
    float4 hv = *reinterpret_cast<const float4*>(h + (size_t)n * HIDN + j4);
    red4(gsum + (size_t)b * HIDN + j4, hv.x, hv.y, hv.z, hv.w);
    if ((t & 63) == 0) atomicAdd(&cnt[b], 1.0f);
}

__global__ void k_gfinal(float* __restrict__ gsum, const float* __restrict__ cnt) {
    int t = blockIdx.x * blockDim.x + threadIdx.x;
    if (t >= BB * (HIDN / 4)) return;
    int b = t >> 6;
    float inv = 1.0f / fmaxf(cnt[b], 1.0f);
    float4 v = *reinterpret_cast<float4*>(gsum + (size_t)t * 4);
    v.x *= inv; v.y *= inv; v.z *= inv; v.w *= inv;
    *reinterpret_cast<float4*>(gsum + (size_t)t * 4) = v;
}

// ---------------- final linear [64 -> 1] -----------------------------------------
__global__ void k_pred(const float* __restrict__ z2, const float* __restrict__ W3,
                       const float* __restrict__ b3, float* __restrict__ out) {
    int w = (blockIdx.x * blockDim.x + threadIdx.x) >> 5;
    int lane = threadIdx.x & 31;
    if (w >= BB) return;
    float s = z2[(size_t)w * 64 + lane] * W3[lane] + z2[(size_t)w * 64 + lane + 32] * W3[lane + 32];
#pragma unroll
    for (int o = 16; o > 0; o >>= 1) s += __shfl_xor_sync(0xFFFFFFFFu, s, o);
    if (lane == 0) out[w] = s + b3[0];
}

// ====================================================================================
#define SYM(p, s) do { void* _t; cudaGetSymbolAddress(&_t, s); p = (decltype(p))_t; } while (0)

extern "C" void kernel_launch(void* const* d_in, const int* in_sizes, int n_in,
                              void* d_out, int out_size) {
    int o = (n_in >= 21) ? 0 : -1;
    const float* x        = (const float*)d_in[0];
    const int*   ei       = (const int*)d_in[1];
    const float* eattr    = (const float*)d_in[2];
    const int*   bidx     = (const int*)d_in[3];
    const float* in_W     = (const float*)d_in[5 + o];
    const float* in_b     = (const float*)d_in[6 + o];
    const float* gat_W    = (const float*)d_in[7 + o];
    const float* att_src  = (const float*)d_in[8 + o];
    const float* att_dst  = (const float*)d_in[9 + o];
    const float* edge_W   = (const float*)d_in[10 + o];
    const float* att_edge = (const float*)d_in[11 + o];
    const float* bn_g     = (const float*)d_in[13 + o];
    const float* bn_b     = (const float*)d_in[14 + o];
    const float* pW1      = (const float*)d_in[15 + o];
    const float* pb1      = (const float*)d_in[16 + o];
    const float* pW2      = (const float*)d_in[17 + o];
    const float* pb2      = (const float*)d_in[18 + o];
    const float* pW3      = (const float*)d_in[19 + o];
    const float* pb3      = (const float*)d_in[20 + o];
    float* out = (float*)d_out;

    const int* src = ei;
    const int* dst = ei + EE;

    float *bufA, *bufB, *xh, *as_, *ad_, *exb, *small, *deg, *lattr, *v, *cnt, *gsum, *z1, *z2;
    int *degi, *roff, *cur, *eidx, *bsum;
    SYM(bufA, g_bufA); SYM(bufB, g_bufB); SYM(xh, g_xh);
    SYM(as_, g_as);    SYM(ad_, g_ad);   SYM(exb, g_ex);
    SYM(small, g_small);
    SYM(deg, g_deg);   SYM(lattr, g_lattr); SYM(v, g_v);
    SYM(cnt, g_cnt);   SYM(gsum, g_gsum); SYM(z1, g_z1); SYM(z2, g_z2);
    SYM(degi, g_degi); SYM(roff, g_roff); SYM(cur, g_cur);
    SYM(eidx, g_eidx); SYM(bsum, g_bsum);

    unsigned* mmax = (unsigned*)(small + SM_MMAX);
    float*    den  = small + SM_DEN;
    float*    mu   = small + SM_MU;
    float*    sq   = small + SM_SQ;

    // idempotent, host-side, capture-safe (no static guard: harness forbids them)
    cudaFuncSetAttribute(k_gemm256, cudaFuncAttributeMaxDynamicSharedMemorySize, G256_SMEM);

    // --- self-loop edge attrs + CSR build + per-layer edge-attention vectors ---
    cudaMemsetAsync(deg, 0, NN * sizeof(float));
    cudaMemsetAsync(degi, 0, NN * sizeof(int));
    cudaMemsetAsync(lattr, 0, (size_t)NN * DE * sizeof(float));
    k_loop_accum<<<(EE + 127) / 128, 128>>>(dst, eattr, deg, lattr, degi);
    k_loop_fin<<<(NN * DE + 255) / 256, 256>>>(deg, lattr);
    k_scan1<<<NBLK_SCAN, 256>>>(degi, roff, bsum);
    k_scan2<<<1, 1024>>>(bsum, NBLK_SCAN);
    k_scan3<<<NBLK_SCAN, 256>>>(roff, bsum);
    k_copyoff<<<(NN + 255) / 256, 256>>>(roff, cur);
    k_fillcsr<<<(EE + 255) / 256, 256>>>(dst, cur, eidx);
    k_veatt<<<LNUM * DE, 128>>>(edge_W, att_edge, v);

    // --- input projection: h = relu(x @ in_W + in_b)  (tf32, ragged K=155) ---
    {
        dim3 grid(2, (NN + 127) / 128);
        k_tf32gemm<<<grid, 256>>>(x, in_W, in_b, bufA, NN, DIN, 1);
    }

    float* curb = bufA;
    float* nxtb = bufB;
    for (int l = 0; l < LNUM; l++) {
        {
            dim3 grid(2, (NN + 127) / 128);
            k_gemm256<<<grid, 256, G256_SMEM>>>(curb, gat_W + (size_t)l * HIDN * HIDN, xh, NN);
        }
        k_att<<<NN, 128>>>(xh, att_src + (size_t)l * NH * CH, att_dst + (size_t)l * NH * CH,
                           as_, ad_);

        cudaMemsetAsync(small, 0, SM_TOTAL * sizeof(float));

        int tE = (EA * NH + 255) / 256;
        k_logits<<<tE, 256>>>(src, dst, eattr, lattr, v + l * DE * NH, as_, ad_, exb, mmax);
        k_exp<<<tE, 256>>>(dst, exb, mmax, den);
        k_aggcsr<<<(NN * 64 + 255) / 256, 256>>>(src, roff, eidx, xh, exb, den, nxtb);

        k_bnstats<<<(NN + 127) / 128, 256>>>(nxtb, mu, sq);
        k_bnapply<<<(int)(((size_t)NN * 64 + 255) / 256), 256>>>(
            nxtb, mu, sq, bn_g + l * HIDN, bn_b + l * HIDN, (l > 0) ? curb : nullptr);

        float* t = curb; curb = nxtb; nxtb = t;
    }

    // --- global mean pool ---
    cudaMemsetAsync(cnt, 0, BB * sizeof(float));
    cudaMemsetAsync(gsum, 0, (size_t)BB * HIDN * sizeof(float));
    k_pool<<<(NN * 64 + 255) / 256, 256>>>(curb, bidx, gsum, cnt);
    k_gfinal<<<(BB * 64 + 255) / 256, 256>>>(gsum, cnt);

    // --- predictor MLP ---
    {
        dim3 g1(1, (BB + 127) / 128);
        k_sgemm<<<g1, 256>>>(gsum, pW1, pb1, z1, BB, HIDN, 128, 1);
        dim3 g2(1, (BB + 127) / 128);
        k_sgemm<<<g2, 256>>>(z1, pW2, pb2, z2, BB, 128, 64, 1);
    }
    k_pred<<<(BB * 32 + 127) / 128, 128>>>(z2, pW3, pb3, out);
}